// round 16
// baseline (speedup 1.0000x reference)
#include <cuda_runtime.h>
#include <cuda_bf16.h>
#include <math.h>

#define Bdim 16
#define Tdim 128
#define NA 64
#define Ddim 256
#define NSs 16
#define Vdim 32000
#define D2 512

// ---------------- scratch (device globals; no allocation) ----------------
__device__ float d_S [Bdim*NA*Ddim];      // states [b][n][d]
__device__ float d_I0[Bdim*NA*Ddim];      // interaction ch0
__device__ float d_I1[Bdim*NA*Ddim];
__device__ float d_G0[Bdim*NA*Ddim];      // sigmoid(gate) ch0
__device__ float d_G1[Bdim*NA*Ddim];
__device__ float d_C0[Bdim*NA*Ddim];      // gelu(cand) ch0
__device__ float d_C1[Bdim*NA*Ddim];
__device__ float d_sens[Tdim*Bdim*NSs*Ddim];  // [t][b][s*256+d]  33.5 MB
__device__ float d_cons[Bdim*Tdim*Ddim];      // [b][t][d]
__device__ float d_hidden[Bdim*Tdim*D2];      // [b*T+t][512]
__device__ float d_iw[NA];
__device__ float d_cw[2];

__device__ __forceinline__ float gelu_f(float x){
    return 0.5f * x * (1.0f + erff(x * 0.70710678118654752440f));
}
__device__ __forceinline__ float sigmoid_f(float x){
    return 1.0f / (1.0f + expf(-x));
}

// ---------------- prep: softmaxes ----------------
__global__ void prep_kernel(const float* __restrict__ ai, const float* __restrict__ cm){
    if (threadIdx.x == 0){
        float mx = -3.4e38f;
        for (int i = 0; i < NA; i++) mx = fmaxf(mx, ai[i]);
        float s = 0.f;
        for (int i = 0; i < NA; i++){ float e = expf(ai[i]-mx); d_iw[i] = e; s += e; }
        float inv = 1.f / s;
        for (int i = 0; i < NA; i++) d_iw[i] *= inv;
        float m2 = fmaxf(cm[0], cm[1]);
        float e0 = expf(cm[0]-m2), e1 = expf(cm[1]-m2);
        d_cw[0] = e0/(e0+e1); d_cw[1] = e1/(e0+e1);
    }
}

__global__ void zero_states(){
    d_S[blockIdx.x*256 + threadIdx.x] = 0.f;   // grid 1024 x 256
}

// ---------------- Phase A: sensory GEMM [2048,256]@[256,4096] ----------------
// row r = t*16+b ; A[r,k] = perception[idx[b,t],k] + pos_emb[t,k]
__global__ __launch_bounds__(256) void sens_gemm(
    const int* __restrict__ idx, const float* __restrict__ perc,
    const float* __restrict__ pos, const float* __restrict__ sw,
    const float* __restrict__ sb)
{
    __shared__ float As[8][128];
    __shared__ float Bs[8][128];
    __shared__ const float* rowp[128];
    __shared__ int rowt[128];
    const int tid = threadIdx.x;
    const int m0 = blockIdx.y * 128, n0 = blockIdx.x * 128;
    if (tid < 128){
        int r = m0 + tid;
        int t = r >> 4, b = r & 15;
        rowp[tid] = perc + (size_t)idx[b*Tdim + t] * Ddim;
        rowt[tid] = t;
    }
    __syncthreads();
    const int tx = tid & 15, ty = tid >> 4;
    float acc[8][8] = {};
    const int am = tid >> 1, ak = (tid & 1) * 4;
    const int bk = tid >> 5, bn = (tid & 31) * 4;
    const float* rp = rowp[am];
    const float* pp = pos + rowt[am]*Ddim;
    for (int k0 = 0; k0 < 256; k0 += 8){
        #pragma unroll
        for (int i = 0; i < 4; i++) As[ak+i][am] = rp[k0+ak+i] + pp[k0+ak+i];
        *(float4*)&Bs[bk][bn] = *(const float4*)&sw[(size_t)(k0+bk)*4096 + n0 + bn];
        __syncthreads();
        #pragma unroll
        for (int k = 0; k < 8; k++){
            float4 a0 = *(const float4*)&As[k][ty*8];
            float4 a1 = *(const float4*)&As[k][ty*8+4];
            float4 b0 = *(const float4*)&Bs[k][tx*8];
            float4 b1 = *(const float4*)&Bs[k][tx*8+4];
            float a[8] = {a0.x,a0.y,a0.z,a0.w,a1.x,a1.y,a1.z,a1.w};
            float bb[8] = {b0.x,b0.y,b0.z,b0.w,b1.x,b1.y,b1.z,b1.w};
            #pragma unroll
            for (int i = 0; i < 8; i++)
                #pragma unroll
                for (int j = 0; j < 8; j++)
                    acc[i][j] = fmaf(a[i], bb[j], acc[i][j]);
        }
        __syncthreads();
    }
    #pragma unroll
    for (int i = 0; i < 8; i++){
        int r = m0 + ty*8 + i;
        float* op = d_sens + (size_t)r*4096 + n0 + tx*8;
        const float* bp = sb + n0 + tx*8;
        #pragma unroll
        for (int j = 0; j < 8; j++) op[j] = acc[i][j] + bp[j];
    }
}

// ---------------- K1: consensus(prev) + sensory add + interaction ----------------
// grid (16 b, 4 dchunk), 256 thr
__global__ __launch_bounds__(256) void step_k1(int t,
    const float* __restrict__ W0, const float* __restrict__ W1)
{
    __shared__ float ss [64][64];
    __shared__ float w0s[64][64];   // [n][m] (transposed)
    __shared__ float w1s[64][64];
    const int b  = blockIdx.x;
    const int dc = blockIdx.y << 6;
    const int tid = threadIdx.x;

    { // load states chunk: 64 agents x 64 cols
        int n = tid >> 2, q = (tid & 3) << 4;
        const float* sp = d_S + ((b<<6)+n)*256 + dc + q;
        *(float4*)&ss[n][q+0]  = *(const float4*)(sp+0);
        *(float4*)&ss[n][q+4]  = *(const float4*)(sp+4);
        *(float4*)&ss[n][q+8]  = *(const float4*)(sp+8);
        *(float4*)&ss[n][q+12] = *(const float4*)(sp+12);
    }
    __syncthreads();

    if (t > 0 && tid < 64){  // consensus of previous step's states
        float acc = 0.f;
        #pragma unroll
        for (int n = 0; n < 64; n++) acc = fmaf(d_iw[n], ss[n][tid], acc);
        d_cons[((b<<7) + (t-1))*256 + dc + tid] = acc;
    }
    if (t == Tdim) return;   // final consensus-only call

    { // load W0/W1 transposed into smem
        int m = tid >> 2, q = (tid & 3) << 4;
        const float* w0p = W0 + (m<<6) + q;
        const float* w1p = W1 + (m<<6) + q;
        #pragma unroll
        for (int i = 0; i < 16; i += 4){
            float4 a = *(const float4*)(w0p+i);
            w0s[q+i][m]=a.x; w0s[q+i+1][m]=a.y; w0s[q+i+2][m]=a.z; w0s[q+i+3][m]=a.w;
            float4 c = *(const float4*)(w1p+i);
            w1s[q+i][m]=c.x; w1s[q+i+1][m]=c.y; w1s[q+i+2][m]=c.z; w1s[q+i+3][m]=c.w;
        }
    }
    __syncthreads();  // consensus readers done before ss mutated; W visible

    { // sensory add to agents 0..15, write back states
        int n  = tid >> 4;            // 0..15
        int cc = (tid & 15) << 2;
        const float* sp = d_sens + (((size_t)t*Bdim + b)*4096) + (n<<8) + dc + cc;
        float4 sv = *(const float4*)sp;
        float* sr = &ss[n][cc];
        sr[0]+=sv.x; sr[1]+=sv.y; sr[2]+=sv.z; sr[3]+=sv.w;
        float* gp = d_S + ((b<<6)+n)*256 + dc + cc;
        *(float4*)gp = make_float4(sr[0],sr[1],sr[2],sr[3]);
    }
    __syncthreads();

    { // interaction = W @ states (both channels), 4m x 4d per thread
        int tm = tid >> 4, td = tid & 15;
        float acc0[4][4] = {};
        float acc1[4][4] = {};
        #pragma unroll 8
        for (int n = 0; n < 64; n++){
            float4 w0v = *(const float4*)&w0s[n][tm<<2];
            float4 w1v = *(const float4*)&w1s[n][tm<<2];
            float4 sv  = *(const float4*)&ss [n][td<<2];
            float wa0[4] = {w0v.x,w0v.y,w0v.z,w0v.w};
            float wa1[4] = {w1v.x,w1v.y,w1v.z,w1v.w};
            float sa [4] = {sv.x, sv.y, sv.z, sv.w};
            #pragma unroll
            for (int i = 0; i < 4; i++)
                #pragma unroll
                for (int j = 0; j < 4; j++){
                    acc0[i][j] = fmaf(wa0[i], sa[j], acc0[i][j]);
                    acc1[i][j] = fmaf(wa1[i], sa[j], acc1[i][j]);
                }
        }
        #pragma unroll
        for (int i = 0; i < 4; i++){
            int m = (tm<<2) + i;
            float* o0 = d_I0 + ((b<<6)+m)*256 + dc + (td<<2);
            float* o1 = d_I1 + ((b<<6)+m)*256 + dc + (td<<2);
            *(float4*)o0 = make_float4(acc0[i][0],acc0[i][1],acc0[i][2],acc0[i][3]);
            *(float4*)o1 = make_float4(acc1[i][0],acc1[i][1],acc1[i][2],acc1[i][3]);
        }
    }
}

// ---------------- K2: gate/cand GEMMs, both channels ----------------
// grid (8 ntile, 8 mtile, 2 ch); ntile<4 -> gate (K=512, A=[S|Ic]); else cand (K=256, A=Ic)
__global__ __launch_bounds__(256) void step_k2(
    const float* __restrict__ gw0, const float* __restrict__ gb0,
    const float* __restrict__ cw0, const float* __restrict__ cb0,
    const float* __restrict__ gw1, const float* __restrict__ gb1,
    const float* __restrict__ cw1, const float* __restrict__ cb1)
{
    __shared__ float As[8][128];
    __shared__ float Bs[8][64];
    const int c  = blockIdx.z;
    const int nt = blockIdx.x;
    const int r0 = blockIdx.y << 7;
    const bool cand = nt >= 4;
    const float* Wp = cand ? (c ? cw1 : cw0) : (c ? gw1 : gw0);
    const float* bp = cand ? (c ? cb1 : cb0) : (c ? gb1 : gb0);
    const float* Ic = c ? d_I1 : d_I0;
    const int n0 = (cand ? nt-4 : nt) << 6;
    const int K  = cand ? 256 : 512;
    const int tid = threadIdx.x;
    const int tx = tid & 15, ty = tid >> 4;
    float acc[8][4] = {};
    const int am = tid >> 1, ak = (tid & 1) << 2;
    const int bk = tid >> 5, bn = (tid & 31) << 1;
    const float* Arow_s = d_S + (r0+am)*256;
    const float* Arow_i = Ic  + (r0+am)*256;

    for (int k0 = 0; k0 < K; k0 += 8){
        int kk = k0 + ak;
        const float* ap = cand ? (Arow_i + kk)
                               : (kk < 256 ? Arow_s + kk : Arow_i + kk - 256);
        float4 av = *(const float4*)ap;
        As[ak][am]=av.x; As[ak+1][am]=av.y; As[ak+2][am]=av.z; As[ak+3][am]=av.w;
        float2 bv = *(const float2*)&Wp[(k0+bk)*256 + n0 + bn];
        Bs[bk][bn] = bv.x; Bs[bk][bn+1] = bv.y;
        __syncthreads();
        #pragma unroll
        for (int k = 0; k < 8; k++){
            float4 a0 = *(const float4*)&As[k][ty<<3];
            float4 a1 = *(const float4*)&As[k][(ty<<3)+4];
            float4 b0 = *(const float4*)&Bs[k][tx<<2];
            float a[8]  = {a0.x,a0.y,a0.z,a0.w,a1.x,a1.y,a1.z,a1.w};
            float bb[4] = {b0.x,b0.y,b0.z,b0.w};
            #pragma unroll
            for (int i = 0; i < 8; i++)
                #pragma unroll
                for (int j = 0; j < 4; j++)
                    acc[i][j] = fmaf(a[i], bb[j], acc[i][j]);
        }
        __syncthreads();
    }
    float* Out = cand ? (c ? d_C1 : d_C0) : (c ? d_G1 : d_G0);
    #pragma unroll
    for (int i = 0; i < 8; i++){
        int r = r0 + (ty<<3) + i;
        #pragma unroll
        for (int j = 0; j < 4; j++){
            int n = n0 + (tx<<2) + j;
            float v = acc[i][j] + bp[n];
            Out[r*256 + n] = cand ? gelu_f(v) : sigmoid_f(v);
        }
    }
}

// ---------------- K3: blend + LayerNorm + channel mix ----------------
__global__ __launch_bounds__(256) void step_k3(
    const float* __restrict__ lg0, const float* __restrict__ lb0,
    const float* __restrict__ lg1, const float* __restrict__ lb1)
{
    const int r = blockIdx.x;       // 0..1023
    const int j = threadIdx.x;      // 0..255
    const int o = (r<<8) + j;
    float s  = d_S[o];
    float g0 = d_G0[o], c0 = d_C0[o];
    float g1 = d_G1[o], c1 = d_C1[o];
    float h0 = g0*c0 + (1.f-g0)*s;
    float h1 = g1*c1 + (1.f-g1)*s;

    float v0 = h0, v1 = h0*h0, v2 = h1, v3 = h1*h1;
    #pragma unroll
    for (int off = 16; off; off >>= 1){
        v0 += __shfl_xor_sync(0xffffffffu, v0, off);
        v1 += __shfl_xor_sync(0xffffffffu, v1, off);
        v2 += __shfl_xor_sync(0xffffffffu, v2, off);
        v3 += __shfl_xor_sync(0xffffffffu, v3, off);
    }
    __shared__ float red[8][4];
    int w = j >> 5, lane = j & 31;
    if (lane == 0){ red[w][0]=v0; red[w][1]=v1; red[w][2]=v2; red[w][3]=v3; }
    __syncthreads();
    float s0=0.f,s1=0.f,s2=0.f,s3=0.f;
    #pragma unroll
    for (int ww = 0; ww < 8; ww++){ s0+=red[ww][0]; s1+=red[ww][1]; s2+=red[ww][2]; s3+=red[ww][3]; }
    const float inv = 1.f/256.f;
    float mu0 = s0*inv, var0 = s1*inv - mu0*mu0;
    float mu1 = s2*inv, var1 = s3*inv - mu1*mu1;
    float o0 = (h0-mu0)*rsqrtf(var0+1e-5f)*lg0[j] + lb0[j];
    float o1 = (h1-mu1)*rsqrtf(var1+1e-5f)*lg1[j] + lb1[j];
    d_S[o] = d_cw[0]*o0 + d_cw[1]*o1;
}

// ---------------- Phase C1: hidden = gelu(cons @ act_w1 + b1) ----------------
// M=2048, N=512, K=256 ; grid (8, 16)
__global__ __launch_bounds__(256) void hidden_gemm(
    const float* __restrict__ w1, const float* __restrict__ b1)
{
    __shared__ float As[8][128];
    __shared__ float Bs[8][64];
    const int tid = threadIdx.x;
    const int tx = tid & 15, ty = tid >> 4;
    const int m0 = blockIdx.y << 7, n0 = blockIdx.x << 6;
    float acc[8][4] = {};
    const int am = tid >> 1, ak = (tid & 1) << 2;
    const int bk = tid >> 5, bn = (tid & 31) << 1;
    const float* Arow = d_cons + (m0+am)*256;
    for (int k0 = 0; k0 < 256; k0 += 8){
        float4 av = *(const float4*)(Arow + k0 + ak);
        As[ak][am]=av.x; As[ak+1][am]=av.y; As[ak+2][am]=av.z; As[ak+3][am]=av.w;
        float2 bv = *(const float2*)&w1[(k0+bk)*512 + n0 + bn];
        Bs[bk][bn] = bv.x; Bs[bk][bn+1] = bv.y;
        __syncthreads();
        #pragma unroll
        for (int k = 0; k < 8; k++){
            float4 a0 = *(const float4*)&As[k][ty<<3];
            float4 a1 = *(const float4*)&As[k][(ty<<3)+4];
            float4 b0 = *(const float4*)&Bs[k][tx<<2];
            float a[8]  = {a0.x,a0.y,a0.z,a0.w,a1.x,a1.y,a1.z,a1.w};
            float bb[4] = {b0.x,b0.y,b0.z,b0.w};
            #pragma unroll
            for (int i = 0; i < 8; i++)
                #pragma unroll
                for (int j = 0; j < 4; j++)
                    acc[i][j] = fmaf(a[i], bb[j], acc[i][j]);
        }
        __syncthreads();
    }
    #pragma unroll
    for (int i = 0; i < 8; i++){
        int r = m0 + (ty<<3) + i;
        #pragma unroll
        for (int j = 0; j < 4; j++){
            int n = n0 + (tx<<2) + j;
            d_hidden[r*512 + n] = gelu_f(acc[i][j] + b1[n]);
        }
    }
}

// ---------------- Phase C2: logits = hidden @ act_w2 + b2 ----------------
// M=2048, N=32000, K=512 ; grid (250, 16)
__global__ __launch_bounds__(256) void logits_gemm(
    const float* __restrict__ w2, const float* __restrict__ b2,
    float* __restrict__ out)
{
    __shared__ float As[8][128];
    __shared__ float Bs[8][128];
    const int tid = threadIdx.x;
    const int tx = tid & 15, ty = tid >> 4;
    const int m0 = blockIdx.y << 7;
    const int n0 = blockIdx.x << 7;
    float acc[8][8] = {};
    const int am = tid >> 1, ak = (tid & 1) << 2;
    const int bk = tid >> 5, bn = (tid & 31) << 2;
    const float* Arow = d_hidden + (m0+am)*512;
    for (int k0 = 0; k0 < 512; k0 += 8){
        float4 av = *(const float4*)(Arow + k0 + ak);
        As[ak][am]=av.x; As[ak+1][am]=av.y; As[ak+2][am]=av.z; As[ak+3][am]=av.w;
        *(float4*)&Bs[bk][bn] = *(const float4*)&w2[(size_t)(k0+bk)*32000 + n0 + bn];
        __syncthreads();
        #pragma unroll
        for (int k = 0; k < 8; k++){
            float4 a0 = *(const float4*)&As[k][ty<<3];
            float4 a1 = *(const float4*)&As[k][(ty<<3)+4];
            float4 b0 = *(const float4*)&Bs[k][tx<<3];
            float4 b1 = *(const float4*)&Bs[k][(tx<<3)+4];
            float a[8]  = {a0.x,a0.y,a0.z,a0.w,a1.x,a1.y,a1.z,a1.w};
            float bb[8] = {b0.x,b0.y,b0.z,b0.w,b1.x,b1.y,b1.z,b1.w};
            #pragma unroll
            for (int i = 0; i < 8; i++)
                #pragma unroll
                for (int j = 0; j < 8; j++)
                    acc[i][j] = fmaf(a[i], bb[j], acc[i][j]);
        }
        __syncthreads();
    }
    #pragma unroll
    for (int i = 0; i < 8; i++){
        size_t r = (size_t)(m0 + (ty<<3) + i);
        float* op = out + r*32000 + n0 + (tx<<3);
        const float* bb2 = b2 + n0 + (tx<<3);
        #pragma unroll
        for (int j = 0; j < 8; j++) op[j] = acc[i][j] + bb2[j];
    }
}

// ---------------- host ----------------
extern "C" void kernel_launch(void* const* d_in, const int* in_sizes, int n_in,
                              void* d_out, int out_size)
{
    // Detect input ordering: find channel_mix (the only size-2 input).
    int cmpos = -1;
    for (int i = 0; i < n_in; i++) if (in_sizes[i] == 2) { cmpos = i; break; }
    int p[25];
    if (cmpos == 5){
        // dict order from setup_inputs()
        const int map[25] = {0,1,2,3,4, 11,12,13,14,15,16,17, 18,19,20,21,22,23,24, 5,6, 7,8,9,10};
        for (int i = 0; i < 25; i++) p[i] = map[i];
    } else {
        // reference() signature order (cmpos == 19) or fallback
        for (int i = 0; i < 25; i++) p[i] = i;
    }
    const int*   idx  = (const int*)  d_in[p[0]];
    const float* perc = (const float*)d_in[p[1]];
    const float* pos  = (const float*)d_in[p[2]];
    const float* sw   = (const float*)d_in[p[3]];
    const float* sb   = (const float*)d_in[p[4]];
    const float* W0   = (const float*)d_in[p[5]];
    const float* gw0  = (const float*)d_in[p[6]];
    const float* gb0  = (const float*)d_in[p[7]];
    const float* cw0  = (const float*)d_in[p[8]];
    const float* cb0  = (const float*)d_in[p[9]];
    const float* lg0  = (const float*)d_in[p[10]];
    const float* lb0  = (const float*)d_in[p[11]];
    const float* W1   = (const float*)d_in[p[12]];
    const float* gw1  = (const float*)d_in[p[13]];
    const float* gb1  = (const float*)d_in[p[14]];
    const float* cw1  = (const float*)d_in[p[15]];
    const float* cb1  = (const float*)d_in[p[16]];
    const float* lg1  = (const float*)d_in[p[17]];
    const float* lb1  = (const float*)d_in[p[18]];
    const float* cm   = (const float*)d_in[p[19]];
    const float* ai   = (const float*)d_in[p[20]];
    const float* aw1  = (const float*)d_in[p[21]];
    const float* ab1  = (const float*)d_in[p[22]];
    const float* aw2  = (const float*)d_in[p[23]];
    const float* ab2  = (const float*)d_in[p[24]];

    zero_states<<<1024, 256>>>();
    prep_kernel<<<1, 32>>>(ai, cm);
    sens_gemm<<<dim3(32, 16), 256>>>(idx, perc, pos, sw, sb);

    for (int t = 0; t < Tdim; t++){
        step_k1<<<dim3(16, 4), 256>>>(t, W0, W1);
        step_k2<<<dim3(8, 8, 2), 256>>>(gw0, gb0, cw0, cb0, gw1, gb1, cw1, cb1);
        step_k3<<<1024, 256>>>(lg0, lb0, lg1, lb1);
    }
    step_k1<<<dim3(16, 4), 256>>>(Tdim, W0, W1);  // final consensus only

    hidden_gemm<<<dim3(8, 16), 256>>>(aw1, ab1);
    logits_gemm<<<dim3(250, 16), 256>>>(aw2, ab2, (float*)d_out);
}

// round 17
// speedup vs baseline: 1.0032x; 1.0032x over previous
#include <cuda_runtime.h>
#include <cuda_bf16.h>
#include <math.h>

#define Bdim 16
#define Tdim 128
#define NA 64
#define Ddim 256
#define NSs 16
#define Vdim 32000
#define D2 512

// ---------------- scratch (device globals; no allocation) ----------------
__device__ float d_S [Bdim*NA*Ddim];      // states [b][n][d]
__device__ float d_I0[Bdim*NA*Ddim];      // interaction ch0
__device__ float d_I1[Bdim*NA*Ddim];
__device__ float d_G0[Bdim*NA*Ddim];      // sigmoid(gate) ch0
__device__ float d_G1[Bdim*NA*Ddim];
__device__ float d_C0[Bdim*NA*Ddim];      // gelu(cand) ch0
__device__ float d_C1[Bdim*NA*Ddim];
__device__ float d_sens[Tdim*Bdim*NSs*Ddim];  // [t][b][s*256+d]  33.5 MB
__device__ float d_cons[Bdim*Tdim*Ddim];      // [b][t][d]
__device__ float d_hidden[Bdim*Tdim*D2];      // [b*T+t][512]
__device__ float d_iw[NA];
__device__ float d_cw[2];

__device__ __forceinline__ float gelu_f(float x){
    return 0.5f * x * (1.0f + erff(x * 0.70710678118654752440f));
}
__device__ __forceinline__ float sigmoid_f(float x){
    return 1.0f / (1.0f + expf(-x));
}

// ---------------- prep: softmaxes ----------------
__global__ void prep_kernel(const float* __restrict__ ai, const float* __restrict__ cm){
    if (threadIdx.x == 0){
        float mx = -3.4e38f;
        for (int i = 0; i < NA; i++) mx = fmaxf(mx, ai[i]);
        float s = 0.f;
        for (int i = 0; i < NA; i++){ float e = expf(ai[i]-mx); d_iw[i] = e; s += e; }
        float inv = 1.f / s;
        for (int i = 0; i < NA; i++) d_iw[i] *= inv;
        float m2 = fmaxf(cm[0], cm[1]);
        float e0 = expf(cm[0]-m2), e1 = expf(cm[1]-m2);
        d_cw[0] = e0/(e0+e1); d_cw[1] = e1/(e0+e1);
    }
}

__global__ void zero_states(){
    d_S[blockIdx.x*256 + threadIdx.x] = 0.f;   // grid 1024 x 256
}

// ---------------- Phase A: sensory GEMM [2048,256]@[256,4096] ----------------
// row r = t*16+b ; A[r,k] = perception[idx[b,t],k] + pos_emb[t,k]
__global__ __launch_bounds__(256) void sens_gemm(
    const int* __restrict__ idx, const float* __restrict__ perc,
    const float* __restrict__ pos, const float* __restrict__ sw,
    const float* __restrict__ sb)
{
    __shared__ float As[8][128];
    __shared__ float Bs[8][128];
    __shared__ const float* rowp[128];
    __shared__ int rowt[128];
    const int tid = threadIdx.x;
    const int m0 = blockIdx.y * 128, n0 = blockIdx.x * 128;
    if (tid < 128){
        int r = m0 + tid;
        int t = r >> 4, b = r & 15;
        rowp[tid] = perc + (size_t)idx[b*Tdim + t] * Ddim;
        rowt[tid] = t;
    }
    __syncthreads();
    const int tx = tid & 15, ty = tid >> 4;
    float acc[8][8] = {};
    const int am = tid >> 1, ak = (tid & 1) * 4;
    const int bk = tid >> 5, bn = (tid & 31) * 4;
    const float* rp = rowp[am];
    const float* pp = pos + rowt[am]*Ddim;
    for (int k0 = 0; k0 < 256; k0 += 8){
        #pragma unroll
        for (int i = 0; i < 4; i++) As[ak+i][am] = rp[k0+ak+i] + pp[k0+ak+i];
        *(float4*)&Bs[bk][bn] = *(const float4*)&sw[(size_t)(k0+bk)*4096 + n0 + bn];
        __syncthreads();
        #pragma unroll
        for (int k = 0; k < 8; k++){
            float4 a0 = *(const float4*)&As[k][ty*8];
            float4 a1 = *(const float4*)&As[k][ty*8+4];
            float4 b0 = *(const float4*)&Bs[k][tx*8];
            float4 b1 = *(const float4*)&Bs[k][tx*8+4];
            float a[8] = {a0.x,a0.y,a0.z,a0.w,a1.x,a1.y,a1.z,a1.w};
            float bb[8] = {b0.x,b0.y,b0.z,b0.w,b1.x,b1.y,b1.z,b1.w};
            #pragma unroll
            for (int i = 0; i < 8; i++)
                #pragma unroll
                for (int j = 0; j < 8; j++)
                    acc[i][j] = fmaf(a[i], bb[j], acc[i][j]);
        }
        __syncthreads();
    }
    #pragma unroll
    for (int i = 0; i < 8; i++){
        int r = m0 + ty*8 + i;
        float* op = d_sens + (size_t)r*4096 + n0 + tx*8;
        const float* bp = sb + n0 + tx*8;
        #pragma unroll
        for (int j = 0; j < 8; j++) op[j] = acc[i][j] + bp[j];
    }
}

// ---------------- K1: consensus(prev) + sensory add + interaction ----------------
// grid (16 b, 4 dchunk), 256 thr
__global__ __launch_bounds__(256) void step_k1(int t,
    const float* __restrict__ W0, const float* __restrict__ W1)
{
    __shared__ float ss [64][64];
    __shared__ float w0s[64][64];   // [n][m] (transposed)
    __shared__ float w1s[64][64];
    const int b  = blockIdx.x;
    const int dc = blockIdx.y << 6;
    const int tid = threadIdx.x;

    { // load states chunk: 64 agents x 64 cols
        int n = tid >> 2, q = (tid & 3) << 4;
        const float* sp = d_S + ((b<<6)+n)*256 + dc + q;
        *(float4*)&ss[n][q+0]  = *(const float4*)(sp+0);
        *(float4*)&ss[n][q+4]  = *(const float4*)(sp+4);
        *(float4*)&ss[n][q+8]  = *(const float4*)(sp+8);
        *(float4*)&ss[n][q+12] = *(const float4*)(sp+12);
    }
    __syncthreads();

    if (t > 0 && tid < 64){  // consensus of previous step's states
        float acc = 0.f;
        #pragma unroll
        for (int n = 0; n < 64; n++) acc = fmaf(d_iw[n], ss[n][tid], acc);
        d_cons[((b<<7) + (t-1))*256 + dc + tid] = acc;
    }
    if (t == Tdim) return;   // final consensus-only call

    { // load W0/W1 transposed into smem
        int m = tid >> 2, q = (tid & 3) << 4;
        const float* w0p = W0 + (m<<6) + q;
        const float* w1p = W1 + (m<<6) + q;
        #pragma unroll
        for (int i = 0; i < 16; i += 4){
            float4 a = *(const float4*)(w0p+i);
            w0s[q+i][m]=a.x; w0s[q+i+1][m]=a.y; w0s[q+i+2][m]=a.z; w0s[q+i+3][m]=a.w;
            float4 c = *(const float4*)(w1p+i);
            w1s[q+i][m]=c.x; w1s[q+i+1][m]=c.y; w1s[q+i+2][m]=c.z; w1s[q+i+3][m]=c.w;
        }
    }
    __syncthreads();  // consensus readers done before ss mutated; W visible

    { // sensory add to agents 0..15, write back states
        int n  = tid >> 4;            // 0..15
        int cc = (tid & 15) << 2;
        const float* sp = d_sens + (((size_t)t*Bdim + b)*4096) + (n<<8) + dc + cc;
        float4 sv = *(const float4*)sp;
        float* sr = &ss[n][cc];
        sr[0]+=sv.x; sr[1]+=sv.y; sr[2]+=sv.z; sr[3]+=sv.w;
        float* gp = d_S + ((b<<6)+n)*256 + dc + cc;
        *(float4*)gp = make_float4(sr[0],sr[1],sr[2],sr[3]);
    }
    __syncthreads();

    { // interaction = W @ states (both channels), 4m x 4d per thread
        int tm = tid >> 4, td = tid & 15;
        float acc0[4][4] = {};
        float acc1[4][4] = {};
        #pragma unroll 8
        for (int n = 0; n < 64; n++){
            float4 w0v = *(const float4*)&w0s[n][tm<<2];
            float4 w1v = *(const float4*)&w1s[n][tm<<2];
            float4 sv  = *(const float4*)&ss [n][td<<2];
            float wa0[4] = {w0v.x,w0v.y,w0v.z,w0v.w};
            float wa1[4] = {w1v.x,w1v.y,w1v.z,w1v.w};
            float sa [4] = {sv.x, sv.y, sv.z, sv.w};
            #pragma unroll
            for (int i = 0; i < 4; i++)
                #pragma unroll
                for (int j = 0; j < 4; j++){
                    acc0[i][j] = fmaf(wa0[i], sa[j], acc0[i][j]);
                    acc1[i][j] = fmaf(wa1[i], sa[j], acc1[i][j]);
                }
        }
        #pragma unroll
        for (int i = 0; i < 4; i++){
            int m = (tm<<2) + i;
            float* o0 = d_I0 + ((b<<6)+m)*256 + dc + (td<<2);
            float* o1 = d_I1 + ((b<<6)+m)*256 + dc + (td<<2);
            *(float4*)o0 = make_float4(acc0[i][0],acc0[i][1],acc0[i][2],acc0[i][3]);
            *(float4*)o1 = make_float4(acc1[i][0],acc1[i][1],acc1[i][2],acc1[i][3]);
        }
    }
}

// ---------------- K2: gate/cand GEMMs, both channels ----------------
// grid (8 ntile, 8 mtile, 2 ch); ntile<4 -> gate (K=512, A=[S|Ic]); else cand (K=256, A=Ic)
__global__ __launch_bounds__(256) void step_k2(
    const float* __restrict__ gw0, const float* __restrict__ gb0,
    const float* __restrict__ cw0, const float* __restrict__ cb0,
    const float* __restrict__ gw1, const float* __restrict__ gb1,
    const float* __restrict__ cw1, const float* __restrict__ cb1)
{
    __shared__ float As[8][128];
    __shared__ float Bs[8][64];
    const int c  = blockIdx.z;
    const int nt = blockIdx.x;
    const int r0 = blockIdx.y << 7;
    const bool cand = nt >= 4;
    const float* Wp = cand ? (c ? cw1 : cw0) : (c ? gw1 : gw0);
    const float* bp = cand ? (c ? cb1 : cb0) : (c ? gb1 : gb0);
    const float* Ic = c ? d_I1 : d_I0;
    const int n0 = (cand ? nt-4 : nt) << 6;
    const int K  = cand ? 256 : 512;
    const int tid = threadIdx.x;
    const int tx = tid & 15, ty = tid >> 4;
    float acc[8][4] = {};
    const int am = tid >> 1, ak = (tid & 1) << 2;
    const int bk = tid >> 5, bn = (tid & 31) << 1;
    const float* Arow_s = d_S + (r0+am)*256;
    const float* Arow_i = Ic  + (r0+am)*256;

    for (int k0 = 0; k0 < K; k0 += 8){
        int kk = k0 + ak;
        const float* ap = cand ? (Arow_i + kk)
                               : (kk < 256 ? Arow_s + kk : Arow_i + kk - 256);
        float4 av = *(const float4*)ap;
        As[ak][am]=av.x; As[ak+1][am]=av.y; As[ak+2][am]=av.z; As[ak+3][am]=av.w;
        float2 bv = *(const float2*)&Wp[(k0+bk)*256 + n0 + bn];
        Bs[bk][bn] = bv.x; Bs[bk][bn+1] = bv.y;
        __syncthreads();
        #pragma unroll
        for (int k = 0; k < 8; k++){
            float4 a0 = *(const float4*)&As[k][ty<<3];
            float4 a1 = *(const float4*)&As[k][(ty<<3)+4];
            float4 b0 = *(const float4*)&Bs[k][tx<<2];
            float a[8]  = {a0.x,a0.y,a0.z,a0.w,a1.x,a1.y,a1.z,a1.w};
            float bb[4] = {b0.x,b0.y,b0.z,b0.w};
            #pragma unroll
            for (int i = 0; i < 8; i++)
                #pragma unroll
                for (int j = 0; j < 4; j++)
                    acc[i][j] = fmaf(a[i], bb[j], acc[i][j]);
        }
        __syncthreads();
    }
    float* Out = cand ? (c ? d_C1 : d_C0) : (c ? d_G1 : d_G0);
    #pragma unroll
    for (int i = 0; i < 8; i++){
        int r = r0 + (ty<<3) + i;
        #pragma unroll
        for (int j = 0; j < 4; j++){
            int n = n0 + (tx<<2) + j;
            float v = acc[i][j] + bp[n];
            Out[r*256 + n] = cand ? gelu_f(v) : sigmoid_f(v);
        }
    }
}

// ---------------- K3: blend + LayerNorm + channel mix ----------------
__global__ __launch_bounds__(256) void step_k3(
    const float* __restrict__ lg0, const float* __restrict__ lb0,
    const float* __restrict__ lg1, const float* __restrict__ lb1)
{
    const int r = blockIdx.x;       // 0..1023
    const int j = threadIdx.x;      // 0..255
    const int o = (r<<8) + j;
    float s  = d_S[o];
    float g0 = d_G0[o], c0 = d_C0[o];
    float g1 = d_G1[o], c1 = d_C1[o];
    float h0 = g0*c0 + (1.f-g0)*s;
    float h1 = g1*c1 + (1.f-g1)*s;

    float v0 = h0, v1 = h0*h0, v2 = h1, v3 = h1*h1;
    #pragma unroll
    for (int off = 16; off; off >>= 1){
        v0 += __shfl_xor_sync(0xffffffffu, v0, off);
        v1 += __shfl_xor_sync(0xffffffffu, v1, off);
        v2 += __shfl_xor_sync(0xffffffffu, v2, off);
        v3 += __shfl_xor_sync(0xffffffffu, v3, off);
    }
    __shared__ float red[8][4];
    int w = j >> 5, lane = j & 31;
    if (lane == 0){ red[w][0]=v0; red[w][1]=v1; red[w][2]=v2; red[w][3]=v3; }
    __syncthreads();
    float s0=0.f,s1=0.f,s2=0.f,s3=0.f;
    #pragma unroll
    for (int ww = 0; ww < 8; ww++){ s0+=red[ww][0]; s1+=red[ww][1]; s2+=red[ww][2]; s3+=red[ww][3]; }
    const float inv = 1.f/256.f;
    float mu0 = s0*inv, var0 = s1*inv - mu0*mu0;
    float mu1 = s2*inv, var1 = s3*inv - mu1*mu1;
    float o0 = (h0-mu0)*rsqrtf(var0+1e-5f)*lg0[j] + lb0[j];
    float o1 = (h1-mu1)*rsqrtf(var1+1e-5f)*lg1[j] + lb1[j];
    d_S[o] = d_cw[0]*o0 + d_cw[1]*o1;
}

// ---------------- Phase C1: hidden = gelu(cons @ act_w1 + b1) ----------------
// M=2048, N=512, K=256 ; grid (8, 16)
__global__ __launch_bounds__(256) void hidden_gemm(
    const float* __restrict__ w1, const float* __restrict__ b1)
{
    __shared__ float As[8][128];
    __shared__ float Bs[8][64];
    const int tid = threadIdx.x;
    const int tx = tid & 15, ty = tid >> 4;
    const int m0 = blockIdx.y << 7, n0 = blockIdx.x << 6;
    float acc[8][4] = {};
    const int am = tid >> 1, ak = (tid & 1) << 2;
    const int bk = tid >> 5, bn = (tid & 31) << 1;
    const float* Arow = d_cons + (m0+am)*256;
    for (int k0 = 0; k0 < 256; k0 += 8){
        float4 av = *(const float4*)(Arow + k0 + ak);
        As[ak][am]=av.x; As[ak+1][am]=av.y; As[ak+2][am]=av.z; As[ak+3][am]=av.w;
        float2 bv = *(const float2*)&w1[(k0+bk)*512 + n0 + bn];
        Bs[bk][bn] = bv.x; Bs[bk][bn+1] = bv.y;
        __syncthreads();
        #pragma unroll
        for (int k = 0; k < 8; k++){
            float4 a0 = *(const float4*)&As[k][ty<<3];
            float4 a1 = *(const float4*)&As[k][(ty<<3)+4];
            float4 b0 = *(const float4*)&Bs[k][tx<<2];
            float a[8]  = {a0.x,a0.y,a0.z,a0.w,a1.x,a1.y,a1.z,a1.w};
            float bb[4] = {b0.x,b0.y,b0.z,b0.w};
            #pragma unroll
            for (int i = 0; i < 8; i++)
                #pragma unroll
                for (int j = 0; j < 4; j++)
                    acc[i][j] = fmaf(a[i], bb[j], acc[i][j]);
        }
        __syncthreads();
    }
    #pragma unroll
    for (int i = 0; i < 8; i++){
        int r = m0 + (ty<<3) + i;
        #pragma unroll
        for (int j = 0; j < 4; j++){
            int n = n0 + (tx<<2) + j;
            d_hidden[r*512 + n] = gelu_f(acc[i][j] + b1[n]);
        }
    }
}

// ---------------- Phase C2: logits = hidden @ act_w2 + b2 ----------------
// M=2048, N=32000, K=512 ; grid (250, 16)
__global__ __launch_bounds__(256) void logits_gemm(
    const float* __restrict__ w2, const float* __restrict__ b2,
    float* __restrict__ out)
{
    __shared__ float As[8][128];
    __shared__ float Bs[8][128];
    const int tid = threadIdx.x;
    const int tx = tid & 15, ty = tid >> 4;
    const int m0 = blockIdx.y << 7;
    const int n0 = blockIdx.x << 7;
    float acc[8][8] = {};
    const int am = tid >> 1, ak = (tid & 1) << 2;
    const int bk = tid >> 5, bn = (tid & 31) << 2;
    const float* Arow = d_hidden + (m0+am)*512;
    for (int k0 = 0; k0 < 512; k0 += 8){
        float4 av = *(const float4*)(Arow + k0 + ak);
        As[ak][am]=av.x; As[ak+1][am]=av.y; As[ak+2][am]=av.z; As[ak+3][am]=av.w;
        *(float4*)&Bs[bk][bn] = *(const float4*)&w2[(size_t)(k0+bk)*32000 + n0 + bn];
        __syncthreads();
        #pragma unroll
        for (int k = 0; k < 8; k++){
            float4 a0 = *(const float4*)&As[k][ty<<3];
            float4 a1 = *(const float4*)&As[k][(ty<<3)+4];
            float4 b0 = *(const float4*)&Bs[k][tx<<3];
            float4 b1 = *(const float4*)&Bs[k][(tx<<3)+4];
            float a[8]  = {a0.x,a0.y,a0.z,a0.w,a1.x,a1.y,a1.z,a1.w};
            float bb[8] = {b0.x,b0.y,b0.z,b0.w,b1.x,b1.y,b1.z,b1.w};
            #pragma unroll
            for (int i = 0; i < 8; i++)
                #pragma unroll
                for (int j = 0; j < 8; j++)
                    acc[i][j] = fmaf(a[i], bb[j], acc[i][j]);
        }
        __syncthreads();
    }
    #pragma unroll
    for (int i = 0; i < 8; i++){
        size_t r = (size_t)(m0 + (ty<<3) + i);
        float* op = out + r*32000 + n0 + (tx<<3);
        const float* bb2 = b2 + n0 + (tx<<3);
        #pragma unroll
        for (int j = 0; j < 8; j++) op[j] = acc[i][j] + bb2[j];
    }
}

// ---------------- host ----------------
extern "C" void kernel_launch(void* const* d_in, const int* in_sizes, int n_in,
                              void* d_out, int out_size)
{
    // Detect input ordering: find channel_mix (the only size-2 input).
    int cmpos = -1;
    for (int i = 0; i < n_in; i++) if (in_sizes[i] == 2) { cmpos = i; break; }
    int p[25];
    if (cmpos == 5){
        // dict order from setup_inputs()
        const int map[25] = {0,1,2,3,4, 11,12,13,14,15,16,17, 18,19,20,21,22,23,24, 5,6, 7,8,9,10};
        for (int i = 0; i < 25; i++) p[i] = map[i];
    } else {
        // reference() signature order (cmpos == 19) or fallback
        for (int i = 0; i < 25; i++) p[i] = i;
    }
    const int*   idx  = (const int*)  d_in[p[0]];
    const float* perc = (const float*)d_in[p[1]];
    const float* pos  = (const float*)d_in[p[2]];
    const float* sw   = (const float*)d_in[p[3]];
    const float* sb   = (const float*)d_in[p[4]];
    const float* W0   = (const float*)d_in[p[5]];
    const float* gw0  = (const float*)d_in[p[6]];
    const float* gb0  = (const float*)d_in[p[7]];
    const float* cw0  = (const float*)d_in[p[8]];
    const float* cb0  = (const float*)d_in[p[9]];
    const float* lg0  = (const float*)d_in[p[10]];
    const float* lb0  = (const float*)d_in[p[11]];
    const float* W1   = (const float*)d_in[p[12]];
    const float* gw1  = (const float*)d_in[p[13]];
    const float* gb1  = (const float*)d_in[p[14]];
    const float* cw1  = (const float*)d_in[p[15]];
    const float* cb1  = (const float*)d_in[p[16]];
    const float* lg1  = (const float*)d_in[p[17]];
    const float* lb1  = (const float*)d_in[p[18]];
    const float* cm   = (const float*)d_in[p[19]];
    const float* ai   = (const float*)d_in[p[20]];
    const float* aw1  = (const float*)d_in[p[21]];
    const float* ab1  = (const float*)d_in[p[22]];
    const float* aw2  = (const float*)d_in[p[23]];
    const float* ab2  = (const float*)d_in[p[24]];

    zero_states<<<1024, 256>>>();
    prep_kernel<<<1, 32>>>(ai, cm);
    sens_gemm<<<dim3(32, 16), 256>>>(idx, perc, pos, sw, sb);

    for (int t = 0; t < Tdim; t++){
        step_k1<<<dim3(16, 4), 256>>>(t, W0, W1);
        step_k2<<<dim3(8, 8, 2), 256>>>(gw0, gb0, cw0, cb0, gw1, gb1, cw1, cb1);
        step_k3<<<1024, 256>>>(lg0, lb0, lg1, lb1);
    }
    step_k1<<<dim3(16, 4), 256>>>(Tdim, W0, W1);  // final consensus only

    hidden_gemm<<<dim3(8, 16), 256>>>(aw1, ab1);
    logits_gemm<<<dim3(250, 16), 256>>>(aw2, ab2, (float*)d_out);
}